// round 16
// baseline (speedup 1.0000x reference)
#include <cuda_runtime.h>
#include <cuda_fp16.h>
#include <cstdint>

// ---------------------------------------------------------------------------
// DivTree fused megakernel v13 (fp16 mma.sync m16n8k16, f32 accum).
// = v11 (warp-autonomous main loop, warp tile 64x32, warp-private B slots,
//   pipelined phase 0, in-place As epilogue, dedicated L3 B buffer)
// + PERSISTENT DE-PHASING (valid because accumulation is commutative and all
//   B state is warp-private):
//   - ks rotation: warp starts its 4 ks-steps at ko=(wid>>2)&3 (4 distinct
//     phases per SMSP) -> ks boundaries stagger.
//   - L2 kt rotation: warp traverses L2's 8 kt-slots in rotated order
//     (rot distinct per warp per SMSP) -> slot boundaries stagger; with no
//     per-slot cross-warp barriers the drift persists, keeping the tensor
//     pipe fed through other warps' LDSM windows.
// ---------------------------------------------------------------------------

// Scratch (allocation-free rule: __device__ globals).
__device__ __half g_wshT[262144];    // 512*512
__device__ __half g_w1T[8388608];    // 32*512*512
__device__ __half g_w2T[524288];     // 32*32*512

// ----------------------------- PTX helpers --------------------------------
__device__ __forceinline__ uint32_t smem_u32(const void* p) {
    uint32_t a;
    asm("{ .reg .u64 t; cvta.to.shared.u64 t, %1; cvt.u32.u64 %0, t; }"
        : "=r"(a) : "l"(p));
    return a;
}
__device__ __forceinline__ void cp_async16(uint32_t dst, const void* src) {
    asm volatile("cp.async.cg.shared.global [%0], [%1], 16;\n" :: "r"(dst), "l"(src));
}
__device__ __forceinline__ void cp_commit() { asm volatile("cp.async.commit_group;\n"); }
template<int N>
__device__ __forceinline__ void cp_wait_group() {
    asm volatile("cp.async.wait_group %0;\n" :: "n"(N));
}
__device__ __forceinline__ void ldsm_x4(uint32_t* r, uint32_t addr) {
    asm volatile("ldmatrix.sync.aligned.m8n8.x4.shared.b16 {%0,%1,%2,%3}, [%4];"
                 : "=r"(r[0]), "=r"(r[1]), "=r"(r[2]), "=r"(r[3]) : "r"(addr));
}
__device__ __forceinline__ void mma_f16(float* c, const uint32_t* a, const uint32_t* b) {
    asm volatile(
        "mma.sync.aligned.m16n8k16.row.col.f32.f16.f16.f32 "
        "{%0,%1,%2,%3}, {%4,%5,%6,%7}, {%8,%9}, {%0,%1,%2,%3};\n"
        : "+f"(c[0]), "+f"(c[1]), "+f"(c[2]), "+f"(c[3])
        : "r"(a[0]), "r"(a[1]), "r"(a[2]), "r"(a[3]), "r"(b[0]), "r"(b[1]));
}
__device__ __forceinline__ void sts32(uint32_t addr, uint32_t v) {
    asm volatile("st.shared.b32 [%0], %1;" :: "r"(addr), "r"(v) : "memory");
}
__device__ __forceinline__ void sts128(uint32_t addr, uint32_t v0, uint32_t v1,
                                       uint32_t v2, uint32_t v3) {
    asm volatile("st.shared.v4.b32 [%0], {%1, %2, %3, %4};"
                 :: "r"(addr), "r"(v0), "r"(v1), "r"(v2), "r"(v3) : "memory");
}
__device__ __forceinline__ uint32_t h2u(__half2 h) { return *(uint32_t*)&h; }

// ------------- prepass: transpose + cvt ALL weights to fp16 ----------------
__global__ void transpose_all_kernel(const float* __restrict__ Wsh,
                                     const float* __restrict__ W1,
                                     const float* __restrict__ W2,
                                     __half* __restrict__ wshT,
                                     __half* __restrict__ w1T,
                                     __half* __restrict__ w2T) {
    const int z = blockIdx.z;
    const float* W;
    __half* WT;
    int N;
    if (z == 0)       { W = Wsh;                              WT = wshT;                              N = 512; }
    else if (z <= 32) { W = W1 + (size_t)(z - 1) * 512 * 512; WT = w1T + (size_t)(z - 1) * 512 * 512; N = 512; }
    else {
        if (blockIdx.x != 0) return;
        W = W2 + (size_t)(z - 33) * 512 * 32;
        WT = w2T + (size_t)(z - 33) * 32 * 512;
        N = 32;
    }
    __shared__ float t[32][33];
    const int k0 = blockIdx.y * 32;
    const int n0 = blockIdx.x * 32;
    const int tx = threadIdx.x, ty = threadIdx.y;
    #pragma unroll
    for (int i = 0; i < 32; i += 8)
        t[ty + i][tx] = W[(size_t)(k0 + ty + i) * N + n0 + tx];
    __syncthreads();
    #pragma unroll
    for (int i = 0; i < 32; i += 8)
        WT[(size_t)(n0 + ty + i) * 512 + k0 + tx] = __float2half_rn(t[tx][ty + i]);
}

// ------------------------------ megakernel ---------------------------------
// SMEM: As 0..64K | BS0 64K..128K | BS1 128K..192K | BS3 192K..224K
constexpr int MEGA_SMEM = 3 * 65536 + 32768 + 1024;   // 230400 <= 232448

__global__ void __launch_bounds__(512, 1)
divtree_mega(const float* __restrict__ x0,
             const __half* __restrict__ wshT, const float* __restrict__ bsh,
             const __half* __restrict__ w1T,  const float* __restrict__ b1,
             const __half* __restrict__ w2T,  const float* __restrict__ b2,
             const int* __restrict__ route,
             float* __restrict__ out)
{
    extern __shared__ char smraw[];
    const uint32_t base = (smem_u32(smraw) + 1023) & ~1023u;
    const uint32_t As  = base;
    const uint32_t BSb = base + 65536;        // BS[s] = BSb + (s&1)*65536
    const uint32_t BS3 = base + 196608;       // dedicated 32KB for L3 B

    const int tid  = threadIdx.x;
    const int lane = tid & 31;
    const int wid  = tid >> 5;                // 0..15, owns cols wid*32..+32
    const int g    = lane >> 2;
    const int tg   = lane & 3;

    // de-phasing constants: distinct per warp within each SMSP
    const int ko  = (wid >> 2) & 3;                          // ks phase
    const int rot = ((wid >> 2) | ((wid & 3) << 2)) & 7;     // L2 kt phase

    const int m0    = blockIdx.x * 64;
    const int agent = blockIdx.y;
    const int e     = __ldg(&route[agent]);

    const __half* w1e = w1T + (size_t)e * 262144;
    const __half* B3  = w2T + (size_t)e * 16384;
    const float*  b1e = b1 + e * 512;

    // kt mapping: L1 sequential (x0 blocks convert progressively);
    // L2 rotated per warp (x1 fully resident after the layer barrier).
    auto kt_of = [&](int s) -> int {
        return (s < 8) ? s : (((s - 8) + rot) & 7);
    };

    // --------- warp-private B-load: slot s in [0,17) -------------------------
    auto load_slot = [&](int s) {
        if (s < 16) {
            const __half* src = (s < 8 ? wshT : w1e) + (size_t)(kt_of(s) * 64);
            const uint32_t dst = BSb + ((uint32_t)(s & 1) << 16);
            const int rbase = wid * 32;
            #pragma unroll
            for (int i = 0; i < 8; ++i) {
                const int ci = i * 32 + lane;          // 0..255 chunk in region
                const int rl = ci >> 3, c = ci & 7;
                const int r  = rbase + rl;
                cp_async16(dst + (uint32_t)r * 128 + ((uint32_t)(c ^ (r & 7)) << 4),
                           src + (size_t)r * 512 + c * 8);
            }
        } else {
            // s == 16: L3 B warp-private: warp wid loads 2KB of BS3
            const int kt = wid >> 1;
            const int rh = (wid & 1) * 16;
            #pragma unroll
            for (int i = 0; i < 4; ++i) {
                const int ci = i * 32 + lane;          // 0..127
                const int rl = rh + (ci >> 3);         // 0..31
                const int c  = ci & 7;
                cp_async16(BS3 + (uint32_t)kt * 4096 + (uint32_t)rl * 128 +
                               ((uint32_t)(c ^ (rl & 7)) << 4),
                           B3 + (size_t)rl * 512 + kt * 64 + c * 8);
            }
        }
        cp_commit();
    };

    load_slot(0);

    // --------- pipelined phase 0: per-block x0 conversion --------------------
    const int xr = tid >> 3;
    const int xc = tid & 7;
    const float* xsrc = x0 + ((size_t)(m0 + xr) * 32 + agent) * 512 + xc * 8;
    const uint32_t xdst = As + (uint32_t)xr * 128 + ((uint32_t)(xc ^ (xr & 7)) << 4);

    {
        const float4 f0 = *(const float4*)xsrc;
        const float4 f1 = *(const float4*)(xsrc + 4);
        sts128(xdst,
               h2u(__floats2half2_rn(f0.x, f0.y)), h2u(__floats2half2_rn(f0.z, f0.w)),
               h2u(__floats2half2_rn(f1.x, f1.y)), h2u(__floats2half2_rn(f1.z, f1.w)));
    }
    float4 xh0 = *(const float4*)(xsrc + 64);      // block 1 held
    float4 xh1 = *(const float4*)(xsrc + 68);
    __syncthreads();   // As block 0 visible

    // --------- layers 1 & 2: 16 warps, warp tile 64x32, full-K acc ----------
    const uint32_t xorv   = (uint32_t)(lane & 7) << 4;
    const uint32_t a_hb4  = (uint32_t)(lane >> 4) << 4;
    const uint32_t b_cad4 = (uint32_t)((lane >> 3) & 1) << 4;

    const uint32_t aRow0 = As + (uint32_t)(lane & 15) * 128;                    // + mi*2048
    const uint32_t bOff0 = (uint32_t)(wid * 32 + (lane & 7) + ((lane >> 4) << 3)) * 128;

    float acc[4][4][4];
    #pragma unroll
    for (int mi = 0; mi < 4; ++mi)
        #pragma unroll
        for (int ni = 0; ni < 4; ++ni)
            #pragma unroll
            for (int q = 0; q < 4; ++q) acc[mi][ni][q] = 0.0f;

    #pragma unroll 1
    for (int s = 0; s < 16; ++s) {
        load_slot(s + 1);              // warp-private WAR: own region of other buf
        cp_wait_group<1>();            // slot s complete (s+1 still in flight)
        __syncwarp();                  // cross-lane visibility within the warp

        const uint32_t aK = (uint32_t)kt_of(s) * 8192;
        const uint32_t bB = BSb + ((uint32_t)(s & 1) << 16);

        #pragma unroll
        for (int ks = 0; ks < 4; ++ks) {
            const uint32_t kq = (uint32_t)(((ks + ko) & 3) * 2) << 4;
            uint32_t af[4][4], bf[2][4];
            ldsm_x4(bf[0], bB + bOff0 + ((kq + b_cad4) ^ xorv));           // ni 0,1
            ldsm_x4(bf[1], bB + bOff0 + 2048u + ((kq + b_cad4) ^ xorv));   // ni 2,3
            #pragma unroll
            for (int mi = 0; mi < 4; ++mi)
                ldsm_x4(af[mi], aRow0 + aK + (uint32_t)mi * 2048 + ((kq + a_hb4) ^ xorv));
            #pragma unroll
            for (int mi = 0; mi < 4; ++mi)
                #pragma unroll
                for (int ni = 0; ni < 4; ++ni)
                    mma_f16(acc[mi][ni], af[mi], &bf[ni >> 1][(ni & 1) * 2]);
        }

        if (s < 7) {
            // store held x0 block s+1 -> As; prefetch block s+2
            sts128(xdst + (uint32_t)(s + 1) * 8192,
                   h2u(__floats2half2_rn(xh0.x, xh0.y)), h2u(__floats2half2_rn(xh0.z, xh0.w)),
                   h2u(__floats2half2_rn(xh1.x, xh1.y)), h2u(__floats2half2_rn(xh1.z, xh1.w)));
            if (s + 2 <= 7) {
                xh0 = *(const float4*)(xsrc + (s + 2) * 64);
                xh1 = *(const float4*)(xsrc + (s + 2) * 64 + 4);
            }
            __syncthreads();           // As block s+1 visible to all warps
        } else if ((s & 7) == 7) {
            // layer epilogue: full convergence (As is rewritten in place)
            __syncthreads();           // all warps done reading As for this layer
            const float* bias = (s < 8) ? bsh : b1e;
            #pragma unroll
            for (int mi = 0; mi < 4; ++mi) {
                #pragma unroll
                for (int ni = 0; ni < 4; ++ni) {
                    const int row = mi * 16 + g;
                    const int cg  = wid * 32 + ni * 8 + tg * 2;
                    const float2 bv = *(const float2*)&bias[cg];
                    const float v0 = fmaxf(acc[mi][ni][0] + bv.x, 0.f);
                    const float v1 = fmaxf(acc[mi][ni][1] + bv.y, 0.f);
                    const float v2 = fmaxf(acc[mi][ni][2] + bv.x, 0.f);
                    const float v3 = fmaxf(acc[mi][ni][3] + bv.y, 0.f);
                    const int kb = cg >> 6, c = cg & 63;
                    const uint32_t a0 = As + (uint32_t)kb * 8192 + (uint32_t)row * 128 +
                                        ((uint32_t)((c >> 3) ^ (row & 7)) << 4) +
                                        (uint32_t)(c & 7) * 2;
                    sts32(a0,        h2u(__floats2half2_rn(v0, v1)));
                    sts32(a0 + 1024, h2u(__floats2half2_rn(v2, v3)));   // row+8
                    acc[mi][ni][0] = 0.f; acc[mi][ni][1] = 0.f;
                    acc[mi][ni][2] = 0.f; acc[mi][ni][3] = 0.f;
                }
            }
            __syncthreads();           // new As visible to all warps
        }
    }

    // --------- phase 3: out[64x32] = hs(As) @ W2T[e] + b2 (B in BS3) --------
    cp_wait_group<0>();
    __syncthreads();
    if (wid < 8) {
        const int warp_m3 = wid >> 1;      // 0..3
        const int warp_n3 = wid & 1;       // 0..1
        const uint32_t aA3 = As + (uint32_t)(warp_m3 * 16 + (lane & 15)) * 128;
        const uint32_t bO3 = (uint32_t)(warp_n3 * 16 + (lane & 7) + ((lane >> 4) << 3)) * 128;

        float a3[2][4];
        #pragma unroll
        for (int ni = 0; ni < 2; ++ni)
            #pragma unroll
            for (int q = 0; q < 4; ++q) a3[ni][q] = 0.0f;

        #pragma unroll
        for (int kt = 0; kt < 8; ++kt) {
            const uint32_t bCur = BS3 + (uint32_t)kt * 4096;
            #pragma unroll
            for (int ks = 0; ks < 4; ++ks) {
                const uint32_t kq = (uint32_t)(2 * ks) << 4;
                uint32_t a4[4], b4[4];
                ldsm_x4(a4, aA3 + (uint32_t)kt * 8192 + ((kq + a_hb4) ^ xorv));
                ldsm_x4(b4, bCur + bO3 + ((kq + b_cad4) ^ xorv));
                mma_f16(a3[0], a4, &b4[0]);
                mma_f16(a3[1], a4, &b4[2]);
            }
        }

        #pragma unroll
        for (int ni = 0; ni < 2; ++ni) {
            const int row = m0 + warp_m3 * 16 + g;
            const int col = warp_n3 * 16 + ni * 8 + tg * 2;
            const float2 bv = *(const float2*)&b2[e * 32 + col];
            *(float2*)&out[((size_t)row * 32 + agent) * 32 + col] =
                make_float2(a3[ni][0] + bv.x, a3[ni][1] + bv.y);
            *(float2*)&out[((size_t)(row + 8) * 32 + agent) * 32 + col] =
                make_float2(a3[ni][2] + bv.x, a3[ni][3] + bv.y);
        }
    }
}

// ------------------------------- launch ------------------------------------
extern "C" void kernel_launch(void* const* d_in, const int* in_sizes, int n_in,
                              void* d_out, int out_size) {
    (void)in_sizes; (void)n_in; (void)out_size;
    const float* x0  = (const float*)d_in[0];   // (4096, 32, 512)
    const float* Wsh = (const float*)d_in[1];   // (512, 512)
    const float* bsh = (const float*)d_in[2];   // (512,)
    const float* W1  = (const float*)d_in[3];   // (32, 512, 512)
    const float* b1  = (const float*)d_in[4];   // (32, 512)
    const float* W2  = (const float*)d_in[5];   // (32, 512, 32)
    const float* b2  = (const float*)d_in[6];   // (32, 32)
    const int*   route = (const int*)d_in[7];   // (32,)
    float* out = (float*)d_out;                 // (4096, 32, 32)

    __half *wshT, *w1T, *w2T;
    cudaGetSymbolAddress((void**)&wshT, g_wshT);
    cudaGetSymbolAddress((void**)&w1T,  g_w1T);
    cudaGetSymbolAddress((void**)&w2T,  g_w2T);

    cudaFuncSetAttribute(divtree_mega,
                         cudaFuncAttributeMaxDynamicSharedMemorySize, MEGA_SMEM);

    transpose_all_kernel<<<dim3(16, 16, 65), dim3(32, 8)>>>(Wsh, W1, W2, wshT, w1T, w2T);

    divtree_mega<<<dim3(64, 32), 512, MEGA_SMEM>>>(
        x0, wshT, bsh, w1T, b1, w2T, b2, route, out);
}

// round 17
// speedup vs baseline: 1.1192x; 1.1192x over previous
#include <cuda_runtime.h>
#include <cuda_fp16.h>
#include <cstdint>

// ---------------------------------------------------------------------------
// DivTree fused megakernel v14 (fp16 mma.sync m16n8k16, f32 accum).
// = v11 EXACTLY (warp-autonomous main loop, warp tile 64x32, warp-private B
//   slots, pipelined phase 0, in-place As epilogue, dedicated L3 B buffer)
// + STRENGTH-REDUCED FILL ADDRESSING: the per-slot B fill addresses are
//   affine in the chunk index i with thread-invariant bases:
//     dst_i = dstD + i*512 ^ ((i&1)<<6),  src_i = srcT + i*4*512
//   with DB = (lane>>3)*128 + (((lane&7)^(lane>>3))<<4),
//        SB = (lane>>3)*512 + (lane&7)*8   (computed once per thread).
//   Removes ~10 ALU ops per cp.async from the hot loop (alu pipe was 21%).
// ---------------------------------------------------------------------------

// Scratch (allocation-free rule: __device__ globals).
__device__ __half g_wshT[262144];    // 512*512
__device__ __half g_w1T[8388608];    // 32*512*512
__device__ __half g_w2T[524288];     // 32*32*512

// ----------------------------- PTX helpers --------------------------------
__device__ __forceinline__ uint32_t smem_u32(const void* p) {
    uint32_t a;
    asm("{ .reg .u64 t; cvta.to.shared.u64 t, %1; cvt.u32.u64 %0, t; }"
        : "=r"(a) : "l"(p));
    return a;
}
__device__ __forceinline__ void cp_async16(uint32_t dst, const void* src) {
    asm volatile("cp.async.cg.shared.global [%0], [%1], 16;\n" :: "r"(dst), "l"(src));
}
__device__ __forceinline__ void cp_commit() { asm volatile("cp.async.commit_group;\n"); }
template<int N>
__device__ __forceinline__ void cp_wait_group() {
    asm volatile("cp.async.wait_group %0;\n" :: "n"(N));
}
__device__ __forceinline__ void ldsm_x4(uint32_t* r, uint32_t addr) {
    asm volatile("ldmatrix.sync.aligned.m8n8.x4.shared.b16 {%0,%1,%2,%3}, [%4];"
                 : "=r"(r[0]), "=r"(r[1]), "=r"(r[2]), "=r"(r[3]) : "r"(addr));
}
__device__ __forceinline__ void mma_f16(float* c, const uint32_t* a, const uint32_t* b) {
    asm volatile(
        "mma.sync.aligned.m16n8k16.row.col.f32.f16.f16.f32 "
        "{%0,%1,%2,%3}, {%4,%5,%6,%7}, {%8,%9}, {%0,%1,%2,%3};\n"
        : "+f"(c[0]), "+f"(c[1]), "+f"(c[2]), "+f"(c[3])
        : "r"(a[0]), "r"(a[1]), "r"(a[2]), "r"(a[3]), "r"(b[0]), "r"(b[1]));
}
__device__ __forceinline__ void sts32(uint32_t addr, uint32_t v) {
    asm volatile("st.shared.b32 [%0], %1;" :: "r"(addr), "r"(v) : "memory");
}
__device__ __forceinline__ void sts128(uint32_t addr, uint32_t v0, uint32_t v1,
                                       uint32_t v2, uint32_t v3) {
    asm volatile("st.shared.v4.b32 [%0], {%1, %2, %3, %4};"
                 :: "r"(addr), "r"(v0), "r"(v1), "r"(v2), "r"(v3) : "memory");
}
__device__ __forceinline__ uint32_t h2u(__half2 h) { return *(uint32_t*)&h; }

// ------------- prepass: transpose + cvt ALL weights to fp16 ----------------
__global__ void transpose_all_kernel(const float* __restrict__ Wsh,
                                     const float* __restrict__ W1,
                                     const float* __restrict__ W2,
                                     __half* __restrict__ wshT,
                                     __half* __restrict__ w1T,
                                     __half* __restrict__ w2T) {
    const int z = blockIdx.z;
    const float* W;
    __half* WT;
    int N;
    if (z == 0)       { W = Wsh;                              WT = wshT;                              N = 512; }
    else if (z <= 32) { W = W1 + (size_t)(z - 1) * 512 * 512; WT = w1T + (size_t)(z - 1) * 512 * 512; N = 512; }
    else {
        if (blockIdx.x != 0) return;
        W = W2 + (size_t)(z - 33) * 512 * 32;
        WT = w2T + (size_t)(z - 33) * 32 * 512;
        N = 32;
    }
    __shared__ float t[32][33];
    const int k0 = blockIdx.y * 32;
    const int n0 = blockIdx.x * 32;
    const int tx = threadIdx.x, ty = threadIdx.y;
    #pragma unroll
    for (int i = 0; i < 32; i += 8)
        t[ty + i][tx] = W[(size_t)(k0 + ty + i) * N + n0 + tx];
    __syncthreads();
    #pragma unroll
    for (int i = 0; i < 32; i += 8)
        WT[(size_t)(n0 + ty + i) * 512 + k0 + tx] = __float2half_rn(t[tx][ty + i]);
}

// ------------------------------ megakernel ---------------------------------
// SMEM: As 0..64K | BS0 64K..128K | BS1 128K..192K | BS3 192K..224K
constexpr int MEGA_SMEM = 3 * 65536 + 32768 + 1024;   // 230400 <= 232448

__global__ void __launch_bounds__(512, 1)
divtree_mega(const float* __restrict__ x0,
             const __half* __restrict__ wshT, const float* __restrict__ bsh,
             const __half* __restrict__ w1T,  const float* __restrict__ b1,
             const __half* __restrict__ w2T,  const float* __restrict__ b2,
             const int* __restrict__ route,
             float* __restrict__ out)
{
    extern __shared__ char smraw[];
    const uint32_t base = (smem_u32(smraw) + 1023) & ~1023u;
    const uint32_t As  = base;
    const uint32_t BSb = base + 65536;        // BS[s] = BSb + (s&1)*65536
    const uint32_t BS3 = base + 196608;       // dedicated 32KB for L3 B

    const int tid  = threadIdx.x;
    const int lane = tid & 31;
    const int wid  = tid >> 5;                // 0..15, owns cols wid*32..+32
    const int g    = lane >> 2;
    const int tg   = lane & 3;

    const int m0    = blockIdx.x * 64;
    const int agent = blockIdx.y;
    const int e     = __ldg(&route[agent]);

    const __half* w1e = w1T + (size_t)e * 262144;
    const __half* B3  = w2T + (size_t)e * 16384;
    const float*  b1e = b1 + e * 512;

    // thread-invariant fill-address bases (verified bit-exact vs swizzle form)
    const uint32_t ls3 = (uint32_t)(lane >> 3);
    const uint32_t lc  = (uint32_t)(lane & 7);
    const uint32_t DB = ls3 * 128 + ((lc ^ ls3) << 4);   // smem offset base
    const uint32_t SB = ls3 * 512 + lc * 8;              // gmem offset base (halves)

    // --------- warp-private B-load: slot s in [0,17) -------------------------
    auto load_slot = [&](int s) {
        if (s < 16) {
            // rows [wid*32, wid*32+32) of slot s; dst_i = dstD+i*512 ^ ((i&1)<<6)
            const __half* srcT = (s < 8 ? wshT : w1e) + (size_t)((s & 7) * 64)
                                 + (size_t)(wid * 32) * 512 + SB;
            const uint32_t dstD = BSb + ((uint32_t)(s & 1) << 16)
                                  + (uint32_t)wid * 4096 + DB;
            #pragma unroll
            for (int i = 0; i < 8; ++i)
                cp_async16((dstD + (uint32_t)i * 512) ^ ((uint32_t)(i & 1) << 6),
                           srcT + i * 4 * 512);
        } else {
            // s == 16: L3 B warp-private: warp wid loads 2KB of BS3
            const int kt = wid >> 1;
            const int rh = (wid & 1) * 16;
            const __half* srcT = B3 + (size_t)rh * 512 + kt * 64 + SB;
            const uint32_t dstD = BS3 + (uint32_t)kt * 4096 + (uint32_t)rh * 128 + DB;
            #pragma unroll
            for (int i = 0; i < 4; ++i)
                cp_async16((dstD + (uint32_t)i * 512) ^ ((uint32_t)(i & 1) << 6),
                           srcT + i * 4 * 512);
        }
        cp_commit();
    };

    load_slot(0);

    // --------- pipelined phase 0: per-block x0 conversion --------------------
    const int xr = tid >> 3;
    const int xc = tid & 7;
    const float* xsrc = x0 + ((size_t)(m0 + xr) * 32 + agent) * 512 + xc * 8;
    const uint32_t xdst = As + (uint32_t)xr * 128 + ((uint32_t)(xc ^ (xr & 7)) << 4);

    {
        const float4 f0 = *(const float4*)xsrc;
        const float4 f1 = *(const float4*)(xsrc + 4);
        sts128(xdst,
               h2u(__floats2half2_rn(f0.x, f0.y)), h2u(__floats2half2_rn(f0.z, f0.w)),
               h2u(__floats2half2_rn(f1.x, f1.y)), h2u(__floats2half2_rn(f1.z, f1.w)));
    }
    float4 xh0 = *(const float4*)(xsrc + 64);      // block 1 held
    float4 xh1 = *(const float4*)(xsrc + 68);
    __syncthreads();   // As block 0 visible

    // --------- layers 1 & 2: 16 warps, warp tile 64x32, full-K acc ----------
    const uint32_t xorv   = (uint32_t)(lane & 7) << 4;
    const uint32_t a_hb4  = (uint32_t)(lane >> 4) << 4;
    const uint32_t b_cad4 = (uint32_t)((lane >> 3) & 1) << 4;

    const uint32_t aRow0 = As + (uint32_t)(lane & 15) * 128;                    // + mi*2048
    const uint32_t bOff0 = (uint32_t)(wid * 32 + (lane & 7) + ((lane >> 4) << 3)) * 128;

    float acc[4][4][4];
    #pragma unroll
    for (int mi = 0; mi < 4; ++mi)
        #pragma unroll
        for (int ni = 0; ni < 4; ++ni)
            #pragma unroll
            for (int q = 0; q < 4; ++q) acc[mi][ni][q] = 0.0f;

    #pragma unroll 1
    for (int s = 0; s < 16; ++s) {
        load_slot(s + 1);              // warp-private WAR: own region of other buf
        cp_wait_group<1>();            // slot s complete (s+1 still in flight)
        __syncwarp();                  // cross-lane visibility within the warp

        const uint32_t aK = (uint32_t)(s & 7) * 8192;
        const uint32_t bB = BSb + ((uint32_t)(s & 1) << 16);

        #pragma unroll
        for (int ks = 0; ks < 4; ++ks) {
            const uint32_t kq = (uint32_t)(2 * ks) << 4;
            uint32_t af[4][4], bf[2][4];
            ldsm_x4(bf[0], bB + bOff0 + ((kq + b_cad4) ^ xorv));           // ni 0,1
            ldsm_x4(bf[1], bB + bOff0 + 2048u + ((kq + b_cad4) ^ xorv));   // ni 2,3
            #pragma unroll
            for (int mi = 0; mi < 4; ++mi)
                ldsm_x4(af[mi], aRow0 + aK + (uint32_t)mi * 2048 + ((kq + a_hb4) ^ xorv));
            #pragma unroll
            for (int mi = 0; mi < 4; ++mi)
                #pragma unroll
                for (int ni = 0; ni < 4; ++ni)
                    mma_f16(acc[mi][ni], af[mi], &bf[ni >> 1][(ni & 1) * 2]);
        }

        if (s < 7) {
            // store held x0 block s+1 -> As; prefetch block s+2
            sts128(xdst + (uint32_t)(s + 1) * 8192,
                   h2u(__floats2half2_rn(xh0.x, xh0.y)), h2u(__floats2half2_rn(xh0.z, xh0.w)),
                   h2u(__floats2half2_rn(xh1.x, xh1.y)), h2u(__floats2half2_rn(xh1.z, xh1.w)));
            if (s + 2 <= 7) {
                xh0 = *(const float4*)(xsrc + (s + 2) * 64);
                xh1 = *(const float4*)(xsrc + (s + 2) * 64 + 4);
            }
            __syncthreads();           // As block s+1 visible to all warps
        } else if ((s & 7) == 7) {
            // layer epilogue: full convergence (As is rewritten in place)
            __syncthreads();           // all warps done reading As for this layer
            const float* bias = (s < 8) ? bsh : b1e;
            #pragma unroll
            for (int mi = 0; mi < 4; ++mi) {
                #pragma unroll
                for (int ni = 0; ni < 4; ++ni) {
                    const int row = mi * 16 + g;
                    const int cg  = wid * 32 + ni * 8 + tg * 2;
                    const float2 bv = *(const float2*)&bias[cg];
                    const float v0 = fmaxf(acc[mi][ni][0] + bv.x, 0.f);
                    const float v1 = fmaxf(acc[mi][ni][1] + bv.y, 0.f);
                    const float v2 = fmaxf(acc[mi][ni][2] + bv.x, 0.f);
                    const float v3 = fmaxf(acc[mi][ni][3] + bv.y, 0.f);
                    const int kb = cg >> 6, c = cg & 63;
                    const uint32_t a0 = As + (uint32_t)kb * 8192 + (uint32_t)row * 128 +
                                        ((uint32_t)((c >> 3) ^ (row & 7)) << 4) +
                                        (uint32_t)(c & 7) * 2;
                    sts32(a0,        h2u(__floats2half2_rn(v0, v1)));
                    sts32(a0 + 1024, h2u(__floats2half2_rn(v2, v3)));   // row+8
                    acc[mi][ni][0] = 0.f; acc[mi][ni][1] = 0.f;
                    acc[mi][ni][2] = 0.f; acc[mi][ni][3] = 0.f;
                }
            }
            __syncthreads();           // new As visible to all warps
        }
    }

    // --------- phase 3: out[64x32] = hs(As) @ W2T[e] + b2 (B in BS3) --------
    cp_wait_group<0>();
    __syncthreads();
    if (wid < 8) {
        const int warp_m3 = wid >> 1;      // 0..3
        const int warp_n3 = wid & 1;       // 0..1
        const uint32_t aA3 = As + (uint32_t)(warp_m3 * 16 + (lane & 15)) * 128;
        const uint32_t bO3 = (uint32_t)(warp_n3 * 16 + (lane & 7) + ((lane >> 4) << 3)) * 128;

        float a3[2][4];
        #pragma unroll
        for (int ni = 0; ni < 2; ++ni)
            #pragma unroll
            for (int q = 0; q < 4; ++q) a3[ni][q] = 0.0f;

        #pragma unroll
        for (int kt = 0; kt < 8; ++kt) {
            const uint32_t bCur = BS3 + (uint32_t)kt * 4096;
            #pragma unroll
            for (int ks = 0; ks < 4; ++ks) {
                const uint32_t kq = (uint32_t)(2 * ks) << 4;
                uint32_t a4[4], b4[4];
                ldsm_x4(a4, aA3 + (uint32_t)kt * 8192 + ((kq + a_hb4) ^ xorv));
                ldsm_x4(b4, bCur + bO3 + ((kq + b_cad4) ^ xorv));
                mma_f16(a3[0], a4, &b4[0]);
                mma_f16(a3[1], a4, &b4[2]);
            }
        }

        #pragma unroll
        for (int ni = 0; ni < 2; ++ni) {
            const int row = m0 + warp_m3 * 16 + g;
            const int col = warp_n3 * 16 + ni * 8 + tg * 2;
            const float2 bv = *(const float2*)&b2[e * 32 + col];
            *(float2*)&out[((size_t)row * 32 + agent) * 32 + col] =
                make_float2(a3[ni][0] + bv.x, a3[ni][1] + bv.y);
            *(float2*)&out[((size_t)(row + 8) * 32 + agent) * 32 + col] =
                make_float2(a3[ni][2] + bv.x, a3[ni][3] + bv.y);
        }
    }
}

// ------------------------------- launch ------------------------------------
extern "C" void kernel_launch(void* const* d_in, const int* in_sizes, int n_in,
                              void* d_out, int out_size) {
    (void)in_sizes; (void)n_in; (void)out_size;
    const float* x0  = (const float*)d_in[0];   // (4096, 32, 512)
    const float* Wsh = (const float*)d_in[1];   // (512, 512)
    const float* bsh = (const float*)d_in[2];   // (512,)
    const float* W1  = (const float*)d_in[3];   // (32, 512, 512)
    const float* b1  = (const float*)d_in[4];   // (32, 512)
    const float* W2  = (const float*)d_in[5];   // (32, 512, 32)
    const float* b2  = (const float*)d_in[6];   // (32, 32)
    const int*   route = (const int*)d_in[7];   // (32,)
    float* out = (float*)d_out;                 // (4096, 32, 32)

    __half *wshT, *w1T, *w2T;
    cudaGetSymbolAddress((void**)&wshT, g_wshT);
    cudaGetSymbolAddress((void**)&w1T,  g_w1T);
    cudaGetSymbolAddress((void**)&w2T,  g_w2T);

    cudaFuncSetAttribute(divtree_mega,
                         cudaFuncAttributeMaxDynamicSharedMemorySize, MEGA_SMEM);

    transpose_all_kernel<<<dim3(16, 16, 65), dim3(32, 8)>>>(Wsh, W1, W2, wshT, w1T, w2T);

    divtree_mega<<<dim3(64, 32), 512, MEGA_SMEM>>>(
        x0, wshT, bsh, w1T, b1, w2T, b2, route, out);
}